// round 12
// baseline (speedup 1.0000x reference)
#include <cuda_runtime.h>
#include <math.h>

#define EPSF      1e-10f
#define SIGINV    7000.0f
#define HEIGHT    256
#define WIDTH     256
#define MAXF      256
#define MAXP      1024
// logf(1e-10f)
#define LOGMIN    -23.025850929940457f
// band where log-miss contribution is non-negligible: sqrt(18/7000) ~= 0.050709
#define BANDEXP   0.0508f
// edge-line cull threshold: band + tile half-diagonal (3.5*sqrt(2)/128) + margin
#define CULLTHR   (0.0508f + 0.03867f + 0.002f)

// per-face precomputed data, COMPACTED to valid faces only (scratch; no allocs)
__device__ float4 g_f0[MAXF];    // x0,y0,x1,y1
__device__ float4 g_f1[MAXF];    // x2,y2,z0,z1
__device__ float4 g_f2[MAXF];    // z2, invA, inv01, inv12
__device__ float  g_i20[MAXF];   // inv20
__device__ float4 g_bb[MAXF];    // expanded bbox: xlo,ylo,xhi,yhi
__device__ float4 g_l0[MAXF];    // outward line eq edge01: ax,ay,c (d=ax*x+ay*y+c)
__device__ float4 g_l1[MAXF];    // edge12
__device__ float4 g_l2[MAXF];    // edge20
__device__ float4 g_uva[MAXF];   // u0,v0,u1,v1
__device__ float2 g_uvb[MAXF];   // u2,v2
__device__ int    g_Fc;          // number of valid faces after compaction

// XLA-style contraction of a*b - c*d: fuse the FIRST multiply.
__device__ __forceinline__ float fused_det(float a, float b, float c, float d) {
    return __fmaf_rn(a, b, -__fmul_rn(c, d));
}

__global__ void face_kernel(const float* __restrict__ pts,
                            const int*   __restrict__ faces,
                            const float* __restrict__ rot,
                            const float* __restrict__ cpos,
                            const float* __restrict__ cproj,
                            const float* __restrict__ uv,
                            const int*   __restrict__ ft,
                            float* __restrict__ out,
                            int P, int F, int normal_off) {
    __shared__ float raw[MAXP * 3];
    __shared__ float sp[MAXP][3];   // camera-space points
    __shared__ float sxy[MAXP][2];  // projected 2D
    __shared__ int   wbase[9];      // per-warp compaction offsets

    int t = threadIdx.x;

    // prefetch face/texture indices early (independent of point transform)
    int i0 = 0, i1 = 0, i2 = 0, t0 = 0, t1 = 0, t2 = 0;
    bool have = t < F;
    if (have) {
        i0 = __ldg(&faces[t * 3 + 0]); i1 = __ldg(&faces[t * 3 + 1]); i2 = __ldg(&faces[t * 3 + 2]);
        t0 = __ldg(&ft[t * 3 + 0]);    t1 = __ldg(&ft[t * 3 + 1]);    t2 = __ldg(&ft[t * 3 + 2]);
    }

    // vectorized staging of pts into shared
    int n = P * 3;
    int nv = n >> 2;                 // # of full float4s
    for (int v = t; v < nv; v += blockDim.x)
        *reinterpret_cast<float4*>(&raw[v * 4]) =
            __ldg(reinterpret_cast<const float4*>(pts) + v);
    for (int r = nv * 4 + t; r < n; r += blockDim.x)
        raw[r] = __ldg(&pts[r]);
    __syncthreads();

    for (int p = t; p < P; p += blockDim.x) {
        float a0 = __fsub_rn(raw[p * 3 + 0], cpos[0]);
        float a1 = __fsub_rn(raw[p * 3 + 1], cpos[1]);
        float a2 = __fsub_rn(raw[p * 3 + 2], cpos[2]);
        float q0 = __fmaf_rn(a2, rot[2], __fmaf_rn(a1, rot[1], __fmul_rn(a0, rot[0])));
        float q1 = __fmaf_rn(a2, rot[5], __fmaf_rn(a1, rot[4], __fmul_rn(a0, rot[3])));
        float q2 = __fmaf_rn(a2, rot[8], __fmaf_rn(a1, rot[7], __fmul_rn(a0, rot[6])));
        sp[p][0] = q0; sp[p][1] = q1; sp[p][2] = q2;
        float x3 = __fmul_rn(q0, cproj[0]);
        float y3 = __fmul_rn(q1, cproj[1]);
        float z3 = __fmul_rn(q2, cproj[2]);
        sxy[p][0] = __fdiv_rn(x3, z3);
        sxy[p][1] = __fdiv_rn(y3, z3);
    }
    __syncthreads();

    // one thread per face (F <= 256)
    int f = t;
    float x0=0,y0=0,x1=0,y1=0,x2=0,y2=0,p0z=0,p1z=0,p2z=0,invA=0,sA=1.0f;
    bool valid = false;

    if (have) {
        float p0x = sp[i0][0], p0y = sp[i0][1]; p0z = sp[i0][2];
        float p1x = sp[i1][0], p1y = sp[i1][1]; p1z = sp[i1][2];
        float p2x = sp[i2][0], p2y = sp[i2][1]; p2z = sp[i2][2];
        x0 = sxy[i0][0]; y0 = sxy[i0][1];
        x1 = sxy[i1][0]; y1 = sxy[i1][1];
        x2 = sxy[i2][0]; y2 = sxy[i2][1];

        // normal = cross(p1-p0, p2-p0) with XLA-style fma contraction.
        float d1x = __fsub_rn(p1x, p0x), d1y = __fsub_rn(p1y, p0y), d1z = __fsub_rn(p1z, p0z);
        float d2x = __fsub_rn(p2x, p0x), d2y = __fsub_rn(p2y, p0y), d2z = __fsub_rn(p2z, p0z);
        float nx = fused_det(d1y, d2z, d1z, d2y);
        float ny = fused_det(d1z, d2x, d1x, d2z);
        float nz = fused_det(d1x, d2y, d1y, d2x);
        float ss = __fmaf_rn(nz, nz, __fmaf_rn(ny, ny, __fmul_rn(nx, nx)));
        float nn = __fsqrt_rn(ss);
        float den = __fadd_rn(nn, EPSF);
        out[normal_off + f * 3 + 0] = __fdiv_rn(nx, den);
        out[normal_off + f * 3 + 1] = __fdiv_rn(ny, den);
        out[normal_off + f * 3 + 2] = __fdiv_rn(nz, den);

        float A = fused_det(__fsub_rn(x1, x0), __fsub_rn(y2, y0),
                            __fsub_rn(x2, x0), __fsub_rn(y1, y0));
        bool aok = fabsf(A) > EPSF;
        invA = aok ? __fdiv_rn(1.0f, A) : 0.0f;
        sA = (A > 0.0f) ? 1.0f : -1.0f;
        valid = aok && (nz > 0.0f);
    }

    // order-preserving block-wide compaction of valid faces
    unsigned m = __ballot_sync(0xffffffffu, valid);
    int lane = t & 31, warp = t >> 5;
    int pre = __popc(m & ((1u << lane) - 1u));
    if (lane == 0) wbase[warp + 1] = __popc(m);
    __syncthreads();
    if (t == 0) {
        wbase[0] = 0;
        for (int w = 0; w < 8; w++) wbase[w + 1] += wbase[w];
        g_Fc = wbase[8];
    }
    __syncthreads();

    if (valid) {
        int c = wbase[warp] + pre;
        float e01x = x1 - x0, e01y = y1 - y0;
        float e12x = x2 - x1, e12y = y2 - y1;
        float e20x = x0 - x2, e20y = y0 - y2;
        float i01 = 1.0f / (e01x * e01x + e01y * e01y + EPSF);
        float i12 = 1.0f / (e12x * e12x + e12y * e12y + EPSF);
        float i20 = 1.0f / (e20x * e20x + e20y * e20y + EPSF);
        g_f0[c]  = make_float4(x0, y0, x1, y1);
        g_f1[c]  = make_float4(x2, y2, p0z, p1z);
        g_f2[c]  = make_float4(p2z, invA, i01, i12);
        g_i20[c] = i20;
        // expanded bbox: outside it, point-to-triangle dist > band -> aa >= 18
        float xlo = fminf(x0, fminf(x1, x2)) - BANDEXP;
        float xhi = fmaxf(x0, fmaxf(x1, x2)) + BANDEXP;
        float ylo = fminf(y0, fminf(y1, y2)) - BANDEXP;
        float yhi = fmaxf(y0, fmaxf(y1, y2)) + BANDEXP;
        g_bb[c] = make_float4(xlo, ylo, xhi, yhi);
        // outward line equations: conservative lower bound on distance
        float r01 = sqrtf(i01), r12 = sqrtf(i12), r20 = sqrtf(i20);
        g_l0[c] = make_float4(sA * r01 * e01y, -sA * r01 * e01x,
                              sA * r01 * (e01x * y0 - e01y * x0), 0.0f);
        g_l1[c] = make_float4(sA * r12 * e12y, -sA * r12 * e12x,
                              sA * r12 * (e12x * y1 - e12y * x1), 0.0f);
        g_l2[c] = make_float4(sA * r20 * e20y, -sA * r20 * e20x,
                              sA * r20 * (e20x * y2 - e20y * x2), 0.0f);
        g_uva[c] = make_float4(uv[t0 * 2], uv[t0 * 2 + 1], uv[t1 * 2], uv[t1 * 2 + 1]);
        g_uvb[c] = make_float2(uv[t2 * 2], uv[t2 * 2 + 1]);
    }
}

__device__ __forceinline__ float edge_d2(float rx, float ry,
                                         float ex, float ey, float inv) {
    float tt = __saturatef((rx * ex + ry * ey) * inv);
    float dx = rx - tt * ex;
    float dy = ry - tt * ey;
    return dx * dx + dy * dy;
}

// center-out permutation of 0..31: 0->15,1->16,2->14,3->17,...
__device__ __forceinline__ int center_out(int i) {
    int off = (i + 1) >> 1;
    return (i & 1) ? (15 + off) : (15 - off);
}

// Tiled raster: block = 8x8 pixel tile x 4 warp-pure face-chunks (256 thr).
// Chunks take INTERLEAVED faces (k = chunk + 4i) to balance work; combine
// uses explicit (z, k) tie-break (smaller compacted k = first occurrence).
// Block order is center-out so heavy central tiles are scheduled first.
__global__ void __launch_bounds__(256)
raster_kernel(const float* __restrict__ tex, float* __restrict__ out,
              int th, int tw) {
    __shared__ float4 s0[MAXF], s1[MAXF], s2[MAXF];
    __shared__ float  si[MAXF];
    __shared__ int    sidx[MAXF];
    __shared__ int    wcnt[8];
    __shared__ float4 r4[4][64];
    __shared__ int    rk[4][64];

    int t = threadIdx.x;
    int Fc = g_Fc;

    // heavy-first tile mapping
    int ti = center_out(blockIdx.x >> 5);
    int tj = center_out(blockIdx.x & 31);
    float txlo = ((float)(tj * 8) + 0.5f) * (1.0f / 128.0f) - 1.0f;
    float txhi = ((float)(tj * 8 + 7) + 0.5f) * (1.0f / 128.0f) - 1.0f;
    float tyhi = 1.0f - (((float)(ti * 8) + 0.5f) * (1.0f / 128.0f));
    float tylo = 1.0f - (((float)(ti * 8 + 7) + 0.5f) * (1.0f / 128.0f));
    float pcx = 0.5f * (txlo + txhi);
    float pcy = 0.5f * (tylo + tyhi);

    // prefilter: one face per thread; all loads independent
    bool keep = false;
    if (t < Fc) {
        float4 bb = __ldg(&g_bb[t]);
        float4 L0 = __ldg(&g_l0[t]);
        float4 L1 = __ldg(&g_l1[t]);
        float4 L2 = __ldg(&g_l2[t]);
        bool bok = !(bb.z < txlo || bb.x > txhi || bb.w < tylo || bb.y > tyhi);
        float d0 = __fmaf_rn(L0.x, pcx, __fmaf_rn(L0.y, pcy, L0.z));
        float d1 = __fmaf_rn(L1.x, pcx, __fmaf_rn(L1.y, pcy, L1.z));
        float d2 = __fmaf_rn(L2.x, pcx, __fmaf_rn(L2.y, pcy, L2.z));
        float dmax = fmaxf(d0, fmaxf(d1, d2));
        keep = bok && (dmax <= CULLTHR);
    }
    unsigned m = __ballot_sync(0xffffffffu, keep);
    int lane = t & 31, warp = t >> 5;
    int pre = __popc(m & ((1u << lane) - 1u));
    if (lane == 0) wcnt[warp] = __popc(m);
    __syncthreads();
    // every thread computes its own base + total (no serial scan / 2nd sync)
    int base = 0, ns = 0;
    #pragma unroll
    for (int w = 0; w < 8; w++) {
        int c = wcnt[w];
        ns += c;
        if (w < warp) base += c;
    }
    if (keep) {
        int c = base + pre;
        s0[c] = g_f0[t]; s1[c] = g_f1[t]; s2[c] = g_f2[t];
        si[c] = g_i20[t]; sidx[c] = t;
    }
    __syncthreads();

    // this thread's pixel + face chunk
    int p = t & 63;             // pixel within tile
    int chunk = t >> 6;         // 0..3; warp-pure
    int row = ti * 8 + (p >> 3);
    int col = tj * 8 + (p & 7);
    float px = ((float)col + 0.5f) * (1.0f / 128.0f) - 1.0f;
    float py = 1.0f - ((float)row + 0.5f) * (1.0f / 128.0f);

    float acc = 0.0f;
    int   cnt = 0;
    float bz = -1e10f, bw0 = 0.0f, bw1 = 0.0f;
    int bk = -1;

    // interleaved faces: balances inside/band work across chunks
    for (int k = chunk; k < ns; k += 4) {
        float4 A4 = s0[k];
        float4 B4 = s1[k];
        float4 C4 = s2[k];
        float r0x = __fsub_rn(px, A4.x), r0y = __fsub_rn(py, A4.y);
        float r1x = __fsub_rn(px, A4.z), r1y = __fsub_rn(py, A4.w);
        float r2x = __fsub_rn(px, B4.x), r2y = __fsub_rn(py, B4.y);
        float invA = C4.y;
        float w0 = __fmul_rn(fused_det(r1x, r2y, r2x, r1y), invA);
        float w1 = __fmul_rn(fused_det(r2x, r0y, r0x, r2y), invA);
        float w2 = __fsub_rn(__fsub_rn(1.0f, w0), w1);
        bool inside = (w0 >= 0.0f) && (w1 >= 0.0f) && (w2 >= 0.0f);

        if (inside) {
            float z = __fmaf_rn(w2, C4.x, __fmaf_rn(w0, B4.z, __fmul_rn(w1, B4.w)));
            if (z > bz) { bz = z; bk = k; bw0 = w0; bw1 = w1; }
            cnt++;
        } else {
            // edge vectors from r's: e_ab = r_a - r_b == v_b - v_a (<=1ulp)
            float e01x = r0x - r1x, e01y = r0y - r1y;
            float e12x = r1x - r2x, e12y = r1y - r2y;
            float e20x = r2x - r0x, e20y = r2y - r0y;
            float d2 = edge_d2(r0x, r0y, e01x, e01y, C4.z);
            d2 = fminf(d2, edge_d2(r1x, r1y, e12x, e12y, C4.w));
            d2 = fminf(d2, edge_d2(r2x, r2y, e20x, e20y, si[k]));
            float aa = d2 * SIGINV;
            if (aa < 18.0f) {
                acc += logf(fmaxf(1.0f - expf(-aa), 1e-10f));
            }
        }
    }
    acc += (float)cnt * LOGMIN;

    r4[chunk][p] = make_float4(acc, bz, bw0, bw1);
    rk[chunk][p] = bk;
    __syncthreads();

    if (t < 64) {
        float4 R = r4[0][t];
        float facc = R.x, fz = R.y, fw0 = R.z, fw1 = R.w;
        int fk = rk[0][t];
        #pragma unroll
        for (int c = 1; c < 4; c++) {
            float4 O = r4[c][t];
            int ok = rk[c][t];
            facc += O.x;
            // explicit (z, k) tie-break: smaller k == first occurrence
            if (ok >= 0 && (fk < 0 || O.y > fz ||
                            (O.y == fz && (unsigned)ok < (unsigned)fk))) {
                fz = O.y; fk = ok; fw0 = O.z; fw1 = O.w;
            }
        }

        int prow = ti * 8 + (t >> 3);
        int pcol = tj * 8 + (t & 7);
        int pix = prow * 256 + pcol;

        // improb
        out[HEIGHT * WIDTH * 3 + pix] = 1.0f - expf(facc);

        // fragment shader
        float c0 = 0.0f, c1 = 0.0f, c2 = 0.0f;
        if (fk >= 0) {
            int bf = sidx[fk];
            float fw2 = __fsub_rn(__fsub_rn(1.0f, fw0), fw1);
            float4 U  = __ldg(&g_uva[bf]);
            float2 U2 = __ldg(&g_uvb[bf]);
            float u = __fmaf_rn(fw2, U2.x, __fmaf_rn(fw0, U.x, __fmul_rn(fw1, U.z)));
            float v = __fmaf_rn(fw2, U2.y, __fmaf_rn(fw0, U.y, __fmul_rn(fw1, U.w)));
            float mask = __fadd_rn(__fadd_rn(fw0, fw1), fw2);

            float x = u * (float)(tw - 1);
            float y = (1.0f - v) * (float)(th - 1);
            float x0f = fminf(fmaxf(floorf(x), 0.0f), (float)(tw - 1));
            float y0f = fminf(fmaxf(floorf(y), 0.0f), (float)(th - 1));
            int x0i = (int)x0f, y0i = (int)y0f;
            int x1i = min(x0i + 1, tw - 1);
            int y1i = min(y0i + 1, th - 1);
            float wx = fminf(fmaxf(x - x0f, 0.0f), 1.0f);
            float wy = fminf(fmaxf(y - y0f, 0.0f), 1.0f);

            int cs = th * tw;
            int b00 = y0i * tw + x0i, b01 = y0i * tw + x1i;
            int b10 = y1i * tw + x0i, b11 = y1i * tw + x1i;

            float col3[3];
            #pragma unroll
            for (int ch = 0; ch < 3; ch++) {
                const float* tc = tex + ch * cs;
                float v00 = __ldg(tc + b00), v01 = __ldg(tc + b01);
                float v10 = __ldg(tc + b10), v11 = __ldg(tc + b11);
                float cc = (v00 * (1.0f - wx) + v01 * wx) * (1.0f - wy)
                         + (v10 * (1.0f - wx) + v11 * wx) * wy;
                col3[ch] = fminf(fmaxf(cc * mask, 0.0f), 1.0f);
            }
            c0 = col3[0]; c1 = col3[1]; c2 = col3[2];
        }
        out[pix * 3 + 0] = c0;
        out[pix * 3 + 1] = c1;
        out[pix * 3 + 2] = c2;
    }
}

extern "C" void kernel_launch(void* const* d_in, const int* in_sizes, int n_in,
                              void* d_out, int out_size) {
    const float* pts   = (const float*)d_in[0];
    const int*   faces = (const int*)  d_in[1];
    const float* rot   = (const float*)d_in[2];
    const float* cpos  = (const float*)d_in[3];
    const float* cproj = (const float*)d_in[4];
    const float* uv    = (const float*)d_in[5];
    const int*   ft    = (const int*)  d_in[6];
    const float* tex   = (const float*)d_in[7];

    int P = in_sizes[0] / 3;
    int F = in_sizes[1] / 3;
    int texels = in_sizes[7] / 3;
    int tw = (int)(sqrt((double)texels) + 0.5);
    int th = texels / tw;

    float* out = (float*)d_out;
    int normal_off = HEIGHT * WIDTH * 3 + HEIGHT * WIDTH;

    face_kernel<<<1, 256>>>(pts, faces, rot, cpos, cproj, uv, ft, out, P, F, normal_off);
    // 32x32 tiles of 8x8 pixels, center-out order
    raster_kernel<<<1024, 256>>>(tex, out, th, tw);
}

// round 13
// speedup vs baseline: 1.0700x; 1.0700x over previous
#include <cuda_runtime.h>
#include <math.h>

#define EPSF      1e-10f
#define SIGINV    7000.0f
#define HEIGHT    256
#define WIDTH     256
#define MAXF      256
#define MAXP      1024
// logf(1e-10f)
#define LOGMIN    -23.025850929940457f
// band where log-miss contribution is non-negligible: sqrt(18/7000) ~= 0.050709
#define BANDEXP   0.0508f
// edge-line cull threshold: band + tile half-diagonal (3.5*sqrt(2)/128) + margin
#define CULLTHR   (0.0508f + 0.03867f + 0.002f)

// per-face precomputed data, COMPACTED to valid faces only (scratch; no allocs)
__device__ float4 g_f0[MAXF];    // x0,y0,x1,y1
__device__ float4 g_f1[MAXF];    // x2,y2,z0,z1
__device__ float4 g_f2[MAXF];    // z2, invA, inv01, inv12
__device__ float  g_i20[MAXF];   // inv20
__device__ float4 g_bb[MAXF];    // expanded bbox: xlo,ylo,xhi,yhi
__device__ float4 g_l0[MAXF];    // outward line eq edge01: ax,ay,c (d=ax*x+ay*y+c)
__device__ float4 g_l1[MAXF];    // edge12
__device__ float4 g_l2[MAXF];    // edge20
__device__ float4 g_uva[MAXF];   // u0,v0,u1,v1
__device__ float2 g_uvb[MAXF];   // u2,v2
__device__ int    g_Fc;          // number of valid faces after compaction

// XLA-style contraction of a*b - c*d: fuse the FIRST multiply.
__device__ __forceinline__ float fused_det(float a, float b, float c, float d) {
    return __fmaf_rn(a, b, -__fmul_rn(c, d));
}

__global__ void face_kernel(const float* __restrict__ pts,
                            const int*   __restrict__ faces,
                            const float* __restrict__ rot,
                            const float* __restrict__ cpos,
                            const float* __restrict__ cproj,
                            const float* __restrict__ uv,
                            const int*   __restrict__ ft,
                            float* __restrict__ out,
                            int P, int F, int normal_off) {
    __shared__ float sp[MAXP][3];   // camera-space points
    __shared__ float sxy[MAXP][2];  // projected 2D
    __shared__ int   wbase[9];      // per-warp compaction offsets

    int t = threadIdx.x;

    // prefetch face/texture indices early (independent of point transform)
    int i0 = 0, i1 = 0, i2 = 0, t0 = 0, t1 = 0, t2 = 0;
    bool have = t < F;
    if (have) {
        i0 = __ldg(&faces[t * 3 + 0]); i1 = __ldg(&faces[t * 3 + 1]); i2 = __ldg(&faces[t * 3 + 2]);
        t0 = __ldg(&ft[t * 3 + 0]);    t1 = __ldg(&ft[t * 3 + 1]);    t2 = __ldg(&ft[t * 3 + 2]);
    }

    for (int p = t; p < P; p += blockDim.x) {
        float a0 = __fsub_rn(pts[p * 3 + 0], cpos[0]);
        float a1 = __fsub_rn(pts[p * 3 + 1], cpos[1]);
        float a2 = __fsub_rn(pts[p * 3 + 2], cpos[2]);
        float q0 = __fmaf_rn(a2, rot[2], __fmaf_rn(a1, rot[1], __fmul_rn(a0, rot[0])));
        float q1 = __fmaf_rn(a2, rot[5], __fmaf_rn(a1, rot[4], __fmul_rn(a0, rot[3])));
        float q2 = __fmaf_rn(a2, rot[8], __fmaf_rn(a1, rot[7], __fmul_rn(a0, rot[6])));
        sp[p][0] = q0; sp[p][1] = q1; sp[p][2] = q2;
        float x3 = __fmul_rn(q0, cproj[0]);
        float y3 = __fmul_rn(q1, cproj[1]);
        float z3 = __fmul_rn(q2, cproj[2]);
        sxy[p][0] = __fdiv_rn(x3, z3);
        sxy[p][1] = __fdiv_rn(y3, z3);
    }
    __syncthreads();

    // one thread per face (F <= 256)
    int f = t;
    float x0=0,y0=0,x1=0,y1=0,x2=0,y2=0,p0z=0,p1z=0,p2z=0,invA=0,sA=1.0f;
    bool valid = false;

    if (have) {
        float p0x = sp[i0][0], p0y = sp[i0][1]; p0z = sp[i0][2];
        float p1x = sp[i1][0], p1y = sp[i1][1]; p1z = sp[i1][2];
        float p2x = sp[i2][0], p2y = sp[i2][1]; p2z = sp[i2][2];
        x0 = sxy[i0][0]; y0 = sxy[i0][1];
        x1 = sxy[i1][0]; y1 = sxy[i1][1];
        x2 = sxy[i2][0]; y2 = sxy[i2][1];

        // normal = cross(p1-p0, p2-p0) with XLA-style fma contraction.
        float d1x = __fsub_rn(p1x, p0x), d1y = __fsub_rn(p1y, p0y), d1z = __fsub_rn(p1z, p0z);
        float d2x = __fsub_rn(p2x, p0x), d2y = __fsub_rn(p2y, p0y), d2z = __fsub_rn(p2z, p0z);
        float nx = fused_det(d1y, d2z, d1z, d2y);
        float ny = fused_det(d1z, d2x, d1x, d2z);
        float nz = fused_det(d1x, d2y, d1y, d2x);
        float ss = __fmaf_rn(nz, nz, __fmaf_rn(ny, ny, __fmul_rn(nx, nx)));
        float nn = __fsqrt_rn(ss);
        float den = __fadd_rn(nn, EPSF);
        out[normal_off + f * 3 + 0] = __fdiv_rn(nx, den);
        out[normal_off + f * 3 + 1] = __fdiv_rn(ny, den);
        out[normal_off + f * 3 + 2] = __fdiv_rn(nz, den);

        float A = fused_det(__fsub_rn(x1, x0), __fsub_rn(y2, y0),
                            __fsub_rn(x2, x0), __fsub_rn(y1, y0));
        bool aok = fabsf(A) > EPSF;
        invA = aok ? __fdiv_rn(1.0f, A) : 0.0f;
        sA = (A > 0.0f) ? 1.0f : -1.0f;
        valid = aok && (nz > 0.0f);
    }

    // order-preserving block-wide compaction of valid faces
    unsigned m = __ballot_sync(0xffffffffu, valid);
    int lane = t & 31, warp = t >> 5;
    int pre = __popc(m & ((1u << lane) - 1u));
    if (lane == 0) wbase[warp + 1] = __popc(m);
    __syncthreads();
    if (t == 0) {
        wbase[0] = 0;
        for (int w = 0; w < 8; w++) wbase[w + 1] += wbase[w];
        g_Fc = wbase[8];
    }
    __syncthreads();

    if (valid) {
        int c = wbase[warp] + pre;
        float e01x = x1 - x0, e01y = y1 - y0;
        float e12x = x2 - x1, e12y = y2 - y1;
        float e20x = x0 - x2, e20y = y0 - y2;
        float i01 = 1.0f / (e01x * e01x + e01y * e01y + EPSF);
        float i12 = 1.0f / (e12x * e12x + e12y * e12y + EPSF);
        float i20 = 1.0f / (e20x * e20x + e20y * e20y + EPSF);
        g_f0[c]  = make_float4(x0, y0, x1, y1);
        g_f1[c]  = make_float4(x2, y2, p0z, p1z);
        g_f2[c]  = make_float4(p2z, invA, i01, i12);
        g_i20[c] = i20;
        // expanded bbox: outside it, point-to-triangle dist > band -> aa >= 18
        float xlo = fminf(x0, fminf(x1, x2)) - BANDEXP;
        float xhi = fmaxf(x0, fmaxf(x1, x2)) + BANDEXP;
        float ylo = fminf(y0, fminf(y1, y2)) - BANDEXP;
        float yhi = fmaxf(y0, fmaxf(y1, y2)) + BANDEXP;
        g_bb[c] = make_float4(xlo, ylo, xhi, yhi);
        // outward line equations: conservative lower bound on distance
        float r01 = sqrtf(i01), r12 = sqrtf(i12), r20 = sqrtf(i20);
        g_l0[c] = make_float4(sA * r01 * e01y, -sA * r01 * e01x,
                              sA * r01 * (e01x * y0 - e01y * x0), 0.0f);
        g_l1[c] = make_float4(sA * r12 * e12y, -sA * r12 * e12x,
                              sA * r12 * (e12x * y1 - e12y * x1), 0.0f);
        g_l2[c] = make_float4(sA * r20 * e20y, -sA * r20 * e20x,
                              sA * r20 * (e20x * y2 - e20y * x2), 0.0f);
        g_uva[c] = make_float4(uv[t0 * 2], uv[t0 * 2 + 1], uv[t1 * 2], uv[t1 * 2 + 1]);
        g_uvb[c] = make_float2(uv[t2 * 2], uv[t2 * 2 + 1]);
    }
}

__device__ __forceinline__ float edge_d2(float rx, float ry,
                                         float ex, float ey, float inv) {
    float tt = __saturatef((rx * ex + ry * ey) * inv);
    float dx = rx - tt * ex;
    float dy = ry - tt * ey;
    return dx * dx + dy * dy;
}

// Tiled raster: block = 8x8 pixel tile x 4 warp-pure face-chunks (256 thr).
// Prefilter per face-tile: 4 INDEPENDENT LDG.128 (bbox + 3 precomputed line
// eqs) + fma/max. Inner loop unrolled 4x so the LDS.128 loads of multiple
// faces are batched (independent MLP) instead of serial load->use chains.
__global__ void __launch_bounds__(256)
raster_kernel(const float* __restrict__ tex, float* __restrict__ out,
              int th, int tw) {
    __shared__ float4 s0[MAXF], s1[MAXF], s2[MAXF];
    __shared__ float  si[MAXF];
    __shared__ int    sidx[MAXF];
    __shared__ int    wbase[9];
    __shared__ float4 r4[4][64];
    __shared__ int    rk[4][64];

    int t = threadIdx.x;
    int Fc = g_Fc;

    // tile pixel-center bounds (32x32 tiles of 8x8 px)
    int ti = blockIdx.x >> 5;   // tile row
    int tj = blockIdx.x & 31;   // tile col
    float txlo = ((float)(tj * 8) + 0.5f) * (1.0f / 128.0f) - 1.0f;
    float txhi = ((float)(tj * 8 + 7) + 0.5f) * (1.0f / 128.0f) - 1.0f;
    float tyhi = 1.0f - (((float)(ti * 8) + 0.5f) * (1.0f / 128.0f));
    float tylo = 1.0f - (((float)(ti * 8 + 7) + 0.5f) * (1.0f / 128.0f));
    float pcx = 0.5f * (txlo + txhi);
    float pcy = 0.5f * (tylo + tyhi);

    // prefilter: one face per thread; all loads independent
    bool keep = false;
    if (t < Fc) {
        float4 bb = __ldg(&g_bb[t]);
        float4 L0 = __ldg(&g_l0[t]);
        float4 L1 = __ldg(&g_l1[t]);
        float4 L2 = __ldg(&g_l2[t]);
        bool bok = !(bb.z < txlo || bb.x > txhi || bb.w < tylo || bb.y > tyhi);
        float d0 = __fmaf_rn(L0.x, pcx, __fmaf_rn(L0.y, pcy, L0.z));
        float d1 = __fmaf_rn(L1.x, pcx, __fmaf_rn(L1.y, pcy, L1.z));
        float d2 = __fmaf_rn(L2.x, pcx, __fmaf_rn(L2.y, pcy, L2.z));
        float dmax = fmaxf(d0, fmaxf(d1, d2));
        keep = bok && (dmax <= CULLTHR);
    }
    unsigned m = __ballot_sync(0xffffffffu, keep);
    int lane = t & 31, warp = t >> 5;
    int pre = __popc(m & ((1u << lane) - 1u));
    if (lane == 0) wbase[warp + 1] = __popc(m);
    __syncthreads();
    if (t == 0) {
        wbase[0] = 0;
        for (int w = 0; w < 8; w++) wbase[w + 1] += wbase[w];
    }
    __syncthreads();
    if (keep) {
        int c = wbase[warp] + pre;
        s0[c] = g_f0[t]; s1[c] = g_f1[t]; s2[c] = g_f2[t];
        si[c] = g_i20[t]; sidx[c] = t;
    }
    __syncthreads();
    int ns = wbase[8];

    // this thread's pixel + face chunk
    int p = t & 63;             // pixel within tile
    int chunk = t >> 6;         // 0..3; warp-pure
    int row = ti * 8 + (p >> 3);
    int col = tj * 8 + (p & 7);
    float px = ((float)col + 0.5f) * (1.0f / 128.0f) - 1.0f;
    float py = 1.0f - ((float)row + 0.5f) * (1.0f / 128.0f);

    int q = (ns + 3) >> 2;
    int kbeg = chunk * q;
    int kend = min(kbeg + q, ns);

    float acc = 0.0f;
    int   cnt = 0;
    float bz = -1e10f, bw0 = 0.0f, bw1 = 0.0f;
    int bk = -1;

    #pragma unroll 4
    for (int k = kbeg; k < kend; k++) {
        float4 A4 = s0[k];
        float4 B4 = s1[k];
        float4 C4 = s2[k];
        float r0x = __fsub_rn(px, A4.x), r0y = __fsub_rn(py, A4.y);
        float r1x = __fsub_rn(px, A4.z), r1y = __fsub_rn(py, A4.w);
        float r2x = __fsub_rn(px, B4.x), r2y = __fsub_rn(py, B4.y);
        float invA = C4.y;
        float w0 = __fmul_rn(fused_det(r1x, r2y, r2x, r1y), invA);
        float w1 = __fmul_rn(fused_det(r2x, r0y, r0x, r2y), invA);
        float w2 = __fsub_rn(__fsub_rn(1.0f, w0), w1);
        bool inside = (w0 >= 0.0f) && (w1 >= 0.0f) && (w2 >= 0.0f);

        if (inside) {
            float z = __fmaf_rn(w2, C4.x, __fmaf_rn(w0, B4.z, __fmul_rn(w1, B4.w)));
            if (z > bz) { bz = z; bk = k; bw0 = w0; bw1 = w1; }
            cnt++;
        } else {
            // edge vectors from r's: e_ab = r_a - r_b == v_b - v_a (<=1ulp)
            float e01x = r0x - r1x, e01y = r0y - r1y;
            float e12x = r1x - r2x, e12y = r1y - r2y;
            float e20x = r2x - r0x, e20y = r2y - r0y;
            float d2 = edge_d2(r0x, r0y, e01x, e01y, C4.z);
            d2 = fminf(d2, edge_d2(r1x, r1y, e12x, e12y, C4.w));
            d2 = fminf(d2, edge_d2(r2x, r2y, e20x, e20y, si[k]));
            float aa = d2 * SIGINV;
            if (aa < 18.0f) {
                acc += logf(fmaxf(1.0f - expf(-aa), 1e-10f));
            }
        }
    }
    acc += (float)cnt * LOGMIN;

    r4[chunk][p] = make_float4(acc, bz, bw0, bw1);
    rk[chunk][p] = bk;
    __syncthreads();

    if (t < 64) {
        float4 R = r4[0][t];
        float facc = R.x, fz = R.y, fw0 = R.z, fw1 = R.w;
        int fk = rk[0][t];
        #pragma unroll
        for (int c = 1; c < 4; c++) {
            float4 O = r4[c][t];
            facc += O.x;
            // ascending chunk order -> strict > keeps first occurrence
            if (O.y > fz) { fz = O.y; fk = rk[c][t]; fw0 = O.z; fw1 = O.w; }
        }

        int prow = ti * 8 + (t >> 3);
        int pcol = tj * 8 + (t & 7);
        int pix = prow * 256 + pcol;

        // improb
        out[HEIGHT * WIDTH * 3 + pix] = 1.0f - expf(facc);

        // fragment shader
        float c0 = 0.0f, c1 = 0.0f, c2 = 0.0f;
        if (fk >= 0) {
            int bf = sidx[fk];
            float fw2 = __fsub_rn(__fsub_rn(1.0f, fw0), fw1);
            float4 U  = __ldg(&g_uva[bf]);
            float2 U2 = __ldg(&g_uvb[bf]);
            float u = __fmaf_rn(fw2, U2.x, __fmaf_rn(fw0, U.x, __fmul_rn(fw1, U.z)));
            float v = __fmaf_rn(fw2, U2.y, __fmaf_rn(fw0, U.y, __fmul_rn(fw1, U.w)));
            float mask = __fadd_rn(__fadd_rn(fw0, fw1), fw2);

            float x = u * (float)(tw - 1);
            float y = (1.0f - v) * (float)(th - 1);
            float x0f = fminf(fmaxf(floorf(x), 0.0f), (float)(tw - 1));
            float y0f = fminf(fmaxf(floorf(y), 0.0f), (float)(th - 1));
            int x0i = (int)x0f, y0i = (int)y0f;
            int x1i = min(x0i + 1, tw - 1);
            int y1i = min(y0i + 1, th - 1);
            float wx = fminf(fmaxf(x - x0f, 0.0f), 1.0f);
            float wy = fminf(fmaxf(y - y0f, 0.0f), 1.0f);

            int cs = th * tw;
            int b00 = y0i * tw + x0i, b01 = y0i * tw + x1i;
            int b10 = y1i * tw + x0i, b11 = y1i * tw + x1i;

            float col3[3];
            #pragma unroll
            for (int ch = 0; ch < 3; ch++) {
                const float* tc = tex + ch * cs;
                float v00 = __ldg(tc + b00), v01 = __ldg(tc + b01);
                float v10 = __ldg(tc + b10), v11 = __ldg(tc + b11);
                float cc = (v00 * (1.0f - wx) + v01 * wx) * (1.0f - wy)
                         + (v10 * (1.0f - wx) + v11 * wx) * wy;
                col3[ch] = fminf(fmaxf(cc * mask, 0.0f), 1.0f);
            }
            c0 = col3[0]; c1 = col3[1]; c2 = col3[2];
        }
        out[pix * 3 + 0] = c0;
        out[pix * 3 + 1] = c1;
        out[pix * 3 + 2] = c2;
    }
}

extern "C" void kernel_launch(void* const* d_in, const int* in_sizes, int n_in,
                              void* d_out, int out_size) {
    const float* pts   = (const float*)d_in[0];
    const int*   faces = (const int*)  d_in[1];
    const float* rot   = (const float*)d_in[2];
    const float* cpos  = (const float*)d_in[3];
    const float* cproj = (const float*)d_in[4];
    const float* uv    = (const float*)d_in[5];
    const int*   ft    = (const int*)  d_in[6];
    const float* tex   = (const float*)d_in[7];

    int P = in_sizes[0] / 3;
    int F = in_sizes[1] / 3;
    int texels = in_sizes[7] / 3;
    int tw = (int)(sqrt((double)texels) + 0.5);
    int th = texels / tw;

    float* out = (float*)d_out;
    int normal_off = HEIGHT * WIDTH * 3 + HEIGHT * WIDTH;

    face_kernel<<<1, 256>>>(pts, faces, rot, cpos, cproj, uv, ft, out, P, F, normal_off);
    // 32x32 tiles of 8x8 pixels
    raster_kernel<<<1024, 256>>>(tex, out, th, tw);
}

// round 14
// speedup vs baseline: 1.1335x; 1.0593x over previous
#include <cuda_runtime.h>
#include <math.h>

#define EPSF      1e-10f
#define SIGINV    7000.0f
#define HEIGHT    256
#define WIDTH     256
#define MAXF      256
#define MAXP      512
// logf(1e-10f)
#define LOGMIN    -23.025850929940457f
// band where log-miss contribution is non-negligible: sqrt(18/7000) ~= 0.050709
#define BANDEXP   0.0508f
// edge-line cull threshold: band + tile half-diagonal (3.5*sqrt(2)/128) + margin
#define CULLTHR   (0.0508f + 0.03867f + 0.002f)

// XLA-style contraction of a*b - c*d: fuse the FIRST multiply.
__device__ __forceinline__ float fused_det(float a, float b, float c, float d) {
    return __fmaf_rn(a, b, -__fmul_rn(c, d));
}

__device__ __forceinline__ float edge_d2(float rx, float ry,
                                         float ex, float ey, float inv) {
    float tt = __saturatef((rx * ex + ry * ey) * inv);
    float dx = rx - tt * ex;
    float dy = ry - tt * ey;
    return dx * dx + dy * dy;
}

// ONE fused kernel: every block (8x8 pixel tile) redundantly recomputes the
// face preprocessing in registers/shared (cheap: P<=512 transforms + F<=256
// face setups), prefilters faces against its tile bbox + edge-line distance
// entirely in registers, compacts survivors to shared (order-preserving),
// then runs the 4-chunk warp-pure face loop. Block 0 also writes normals.
// Shared is phase-overlaid: point buffers (10KB) then survivor arrays (14KB).
__global__ void __launch_bounds__(256)
fused_kernel(const float* __restrict__ pts,
             const int*   __restrict__ faces,
             const float* __restrict__ rot,
             const float* __restrict__ cpos,
             const float* __restrict__ cproj,
             const float* __restrict__ uv,
             const int*   __restrict__ ft,
             const float* __restrict__ tex,
             float* __restrict__ out,
             int P, int F, int th, int tw, int normal_off) {
    // overlaid shared: phase A = point buffers, phase B = survivor arrays
    __shared__ __align__(16) char shraw[MAXF * (16 * 3 + 4 + 4)];  // 14336 B
    __shared__ int    wbase[9];
    __shared__ float4 r4[4][64];
    __shared__ int    rk[4][64];

    float* sp  = (float*)shraw;          // [MAXP*3] camera-space points
    float* sxy = sp + MAXP * 3;          // [MAXP*2] projected 2D
    float4* s0 = (float4*)shraw;         // survivors (after phase A done)
    float4* s1 = s0 + MAXF;
    float4* s2 = s1 + MAXF;
    float*  si = (float*)(s2 + MAXF);
    int*  sidx = (int*)(si + MAXF);

    int t = threadIdx.x;
    int ti = blockIdx.x >> 5;   // tile row
    int tj = blockIdx.x & 31;   // tile col

    // tile pixel-center bounds
    float txlo = ((float)(tj * 8) + 0.5f) * (1.0f / 128.0f) - 1.0f;
    float txhi = ((float)(tj * 8 + 7) + 0.5f) * (1.0f / 128.0f) - 1.0f;
    float tyhi = 1.0f - (((float)(ti * 8) + 0.5f) * (1.0f / 128.0f));
    float tylo = 1.0f - (((float)(ti * 8 + 7) + 0.5f) * (1.0f / 128.0f));
    float pcx = 0.5f * (txlo + txhi);
    float pcy = 0.5f * (tylo + tyhi);

    // ---- phase A: transform points (identical math to reference) ----
    for (int p = t; p < P; p += blockDim.x) {
        float a0 = __fsub_rn(pts[p * 3 + 0], cpos[0]);
        float a1 = __fsub_rn(pts[p * 3 + 1], cpos[1]);
        float a2 = __fsub_rn(pts[p * 3 + 2], cpos[2]);
        float q0 = __fmaf_rn(a2, rot[2], __fmaf_rn(a1, rot[1], __fmul_rn(a0, rot[0])));
        float q1 = __fmaf_rn(a2, rot[5], __fmaf_rn(a1, rot[4], __fmul_rn(a0, rot[3])));
        float q2 = __fmaf_rn(a2, rot[8], __fmaf_rn(a1, rot[7], __fmul_rn(a0, rot[6])));
        sp[p * 3 + 0] = q0; sp[p * 3 + 1] = q1; sp[p * 3 + 2] = q2;
        float x3 = __fmul_rn(q0, cproj[0]);
        float y3 = __fmul_rn(q1, cproj[1]);
        float z3 = __fmul_rn(q2, cproj[2]);
        sxy[p * 2 + 0] = __fdiv_rn(x3, z3);
        sxy[p * 2 + 1] = __fdiv_rn(y3, z3);
    }
    __syncthreads();

    // ---- phase B: per-face setup in REGISTERS (one thread per face) ----
    bool have = t < F;
    float x0=0,y0=0,x1=0,y1=0,x2=0,y2=0,p0z=0,p1z=0,p2z=0,invA=0,sA=1.0f;
    bool keep = false;

    if (have) {
        int i0 = faces[t * 3 + 0], i1 = faces[t * 3 + 1], i2 = faces[t * 3 + 2];
        float p0x = sp[i0 * 3 + 0], p0y = sp[i0 * 3 + 1]; p0z = sp[i0 * 3 + 2];
        float p1x = sp[i1 * 3 + 0], p1y = sp[i1 * 3 + 1]; p1z = sp[i1 * 3 + 2];
        float p2x = sp[i2 * 3 + 0], p2y = sp[i2 * 3 + 1]; p2z = sp[i2 * 3 + 2];
        x0 = sxy[i0 * 2 + 0]; y0 = sxy[i0 * 2 + 1];
        x1 = sxy[i1 * 2 + 0]; y1 = sxy[i1 * 2 + 1];
        x2 = sxy[i2 * 2 + 0]; y2 = sxy[i2 * 2 + 1];

        // normal = cross(p1-p0, p2-p0) with XLA-style fma contraction.
        float d1x = __fsub_rn(p1x, p0x), d1y = __fsub_rn(p1y, p0y), d1z = __fsub_rn(p1z, p0z);
        float d2x = __fsub_rn(p2x, p0x), d2y = __fsub_rn(p2y, p0y), d2z = __fsub_rn(p2z, p0z);
        float nx = fused_det(d1y, d2z, d1z, d2y);
        float ny = fused_det(d1z, d2x, d1x, d2z);
        float nz = fused_det(d1x, d2y, d1y, d2x);

        if (blockIdx.x == 0) {
            float ss = __fmaf_rn(nz, nz, __fmaf_rn(ny, ny, __fmul_rn(nx, nx)));
            float nn = __fsqrt_rn(ss);
            float den = __fadd_rn(nn, EPSF);
            out[normal_off + t * 3 + 0] = __fdiv_rn(nx, den);
            out[normal_off + t * 3 + 1] = __fdiv_rn(ny, den);
            out[normal_off + t * 3 + 2] = __fdiv_rn(nz, den);
        }

        float A = fused_det(__fsub_rn(x1, x0), __fsub_rn(y2, y0),
                            __fsub_rn(x2, x0), __fsub_rn(y1, y0));
        bool aok = fabsf(A) > EPSF;
        invA = aok ? __fdiv_rn(1.0f, A) : 0.0f;
        sA = (A > 0.0f) ? 1.0f : -1.0f;
        bool valid = aok && (nz > 0.0f);

        if (valid) {
            // tile prefilter in registers: expanded bbox + edge-line cull
            float xlo = fminf(x0, fminf(x1, x2)) - BANDEXP;
            float xhi = fmaxf(x0, fmaxf(x1, x2)) + BANDEXP;
            float ylo = fminf(y0, fminf(y1, y2)) - BANDEXP;
            float yhi = fmaxf(y0, fmaxf(y1, y2)) + BANDEXP;
            bool bok = !(xhi < txlo || xlo > txhi || yhi < tylo || ylo > tyhi);
            if (bok) {
                float e01x = x1 - x0, e01y = y1 - y0;
                float e12x = x2 - x1, e12y = y2 - y1;
                float e20x = x0 - x2, e20y = y0 - y2;
                float i01 = 1.0f / (e01x * e01x + e01y * e01y + EPSF);
                float i12 = 1.0f / (e12x * e12x + e12y * e12y + EPSF);
                float i20 = 1.0f / (e20x * e20x + e20y * e20y + EPSF);
                // outward line distances at tile center (conservative)
                float c01 = e01x * (pcy - y0) - e01y * (pcx - x0);
                float c12 = e12x * (pcy - y1) - e12y * (pcx - x1);
                float c20 = e20x * (pcy - y2) - e20y * (pcx - x2);
                float d01 = -sA * c01 * sqrtf(i01);
                float d12 = -sA * c12 * sqrtf(i12);
                float d20 = -sA * c20 * sqrtf(i20);
                keep = fmaxf(d01, fmaxf(d12, d20)) <= CULLTHR;
            }
        }
    }

    // order-preserving compaction of kept faces into shared survivor arrays
    unsigned m = __ballot_sync(0xffffffffu, keep);
    int lane = t & 31, warp = t >> 5;
    int pre = __popc(m & ((1u << lane) - 1u));
    if (lane == 0) wbase[warp + 1] = __popc(m);
    __syncthreads();   // also: all sp/sxy reads complete before overlay write
    if (t == 0) {
        wbase[0] = 0;
        #pragma unroll
        for (int w = 0; w < 8; w++) wbase[w + 1] += wbase[w];
    }
    __syncthreads();
    if (keep) {
        int c = wbase[warp] + pre;
        float e01x = x1 - x0, e01y = y1 - y0;
        float e12x = x2 - x1, e12y = y2 - y1;
        float e20x = x0 - x2, e20y = y0 - y2;
        float i01 = 1.0f / (e01x * e01x + e01y * e01y + EPSF);
        float i12 = 1.0f / (e12x * e12x + e12y * e12y + EPSF);
        float i20 = 1.0f / (e20x * e20x + e20y * e20y + EPSF);
        s0[c] = make_float4(x0, y0, x1, y1);
        s1[c] = make_float4(x2, y2, p0z, p1z);
        s2[c] = make_float4(p2z, invA, i01, i12);
        si[c] = i20;
        sidx[c] = t;      // original face index (for uv fetch)
    }
    __syncthreads();
    int ns = wbase[8];

    // ---- phase C: face loop (identical math to R10 champion) ----
    int p = t & 63;             // pixel within tile
    int chunk = t >> 6;         // 0..3; warp-pure
    int row = ti * 8 + (p >> 3);
    int col = tj * 8 + (p & 7);
    float px = ((float)col + 0.5f) * (1.0f / 128.0f) - 1.0f;
    float py = 1.0f - ((float)row + 0.5f) * (1.0f / 128.0f);

    int q = (ns + 3) >> 2;
    int kbeg = chunk * q;
    int kend = min(kbeg + q, ns);

    float acc = 0.0f;
    int   cnt = 0;
    float bz = -1e10f, bw0 = 0.0f, bw1 = 0.0f;
    int bk = -1;

    for (int k = kbeg; k < kend; k++) {
        float4 A4 = s0[k];
        float4 B4 = s1[k];
        float4 C4 = s2[k];
        float r0x = __fsub_rn(px, A4.x), r0y = __fsub_rn(py, A4.y);
        float r1x = __fsub_rn(px, A4.z), r1y = __fsub_rn(py, A4.w);
        float r2x = __fsub_rn(px, B4.x), r2y = __fsub_rn(py, B4.y);
        float invAk = C4.y;
        float w0 = __fmul_rn(fused_det(r1x, r2y, r2x, r1y), invAk);
        float w1 = __fmul_rn(fused_det(r2x, r0y, r0x, r2y), invAk);
        float w2 = __fsub_rn(__fsub_rn(1.0f, w0), w1);
        bool inside = (w0 >= 0.0f) && (w1 >= 0.0f) && (w2 >= 0.0f);

        if (inside) {
            float z = __fmaf_rn(w2, C4.x, __fmaf_rn(w0, B4.z, __fmul_rn(w1, B4.w)));
            if (z > bz) { bz = z; bk = k; bw0 = w0; bw1 = w1; }
            cnt++;
        } else {
            // edge vectors from r's: e_ab = r_a - r_b == v_b - v_a (<=1ulp)
            float e01x = r0x - r1x, e01y = r0y - r1y;
            float e12x = r1x - r2x, e12y = r1y - r2y;
            float e20x = r2x - r0x, e20y = r2y - r0y;
            float d2 = edge_d2(r0x, r0y, e01x, e01y, C4.z);
            d2 = fminf(d2, edge_d2(r1x, r1y, e12x, e12y, C4.w));
            d2 = fminf(d2, edge_d2(r2x, r2y, e20x, e20y, si[k]));
            float aa = d2 * SIGINV;
            if (aa < 18.0f) {
                acc += logf(fmaxf(1.0f - expf(-aa), 1e-10f));
            }
        }
    }
    acc += (float)cnt * LOGMIN;

    r4[chunk][p] = make_float4(acc, bz, bw0, bw1);
    rk[chunk][p] = bk;
    __syncthreads();

    if (t < 64) {
        float4 R = r4[0][t];
        float facc = R.x, fz = R.y, fw0 = R.z, fw1 = R.w;
        int fk = rk[0][t];
        #pragma unroll
        for (int c = 1; c < 4; c++) {
            float4 O = r4[c][t];
            facc += O.x;
            // ascending chunk order -> strict > keeps first occurrence
            if (O.y > fz) { fz = O.y; fk = rk[c][t]; fw0 = O.z; fw1 = O.w; }
        }

        int prow = ti * 8 + (t >> 3);
        int pcol = tj * 8 + (t & 7);
        int pix = prow * 256 + pcol;

        // improb
        out[HEIGHT * WIDTH * 3 + pix] = 1.0f - expf(facc);

        // fragment shader
        float c0 = 0.0f, c1 = 0.0f, c2 = 0.0f;
        if (fk >= 0) {
            int bf = sidx[fk];   // original face id
            int t0 = __ldg(&ft[bf * 3 + 0]);
            int t1 = __ldg(&ft[bf * 3 + 1]);
            int t2 = __ldg(&ft[bf * 3 + 2]);
            float u0 = __ldg(&uv[t0 * 2]), v0 = __ldg(&uv[t0 * 2 + 1]);
            float u1 = __ldg(&uv[t1 * 2]), v1 = __ldg(&uv[t1 * 2 + 1]);
            float u2 = __ldg(&uv[t2 * 2]), v2 = __ldg(&uv[t2 * 2 + 1]);
            float fw2 = __fsub_rn(__fsub_rn(1.0f, fw0), fw1);
            float u = __fmaf_rn(fw2, u2, __fmaf_rn(fw0, u0, __fmul_rn(fw1, u1)));
            float v = __fmaf_rn(fw2, v2, __fmaf_rn(fw0, v0, __fmul_rn(fw1, v1)));
            float mask = __fadd_rn(__fadd_rn(fw0, fw1), fw2);

            float x = u * (float)(tw - 1);
            float y = (1.0f - v) * (float)(th - 1);
            float x0f = fminf(fmaxf(floorf(x), 0.0f), (float)(tw - 1));
            float y0f = fminf(fmaxf(floorf(y), 0.0f), (float)(th - 1));
            int x0i = (int)x0f, y0i = (int)y0f;
            int x1i = min(x0i + 1, tw - 1);
            int y1i = min(y0i + 1, th - 1);
            float wx = fminf(fmaxf(x - x0f, 0.0f), 1.0f);
            float wy = fminf(fmaxf(y - y0f, 0.0f), 1.0f);

            int cs = th * tw;
            int b00 = y0i * tw + x0i, b01 = y0i * tw + x1i;
            int b10 = y1i * tw + x0i, b11 = y1i * tw + x1i;

            float col3[3];
            #pragma unroll
            for (int ch = 0; ch < 3; ch++) {
                const float* tc = tex + ch * cs;
                float v00 = __ldg(tc + b00), v01 = __ldg(tc + b01);
                float v10 = __ldg(tc + b10), v11 = __ldg(tc + b11);
                float cc = (v00 * (1.0f - wx) + v01 * wx) * (1.0f - wy)
                         + (v10 * (1.0f - wx) + v11 * wx) * wy;
                col3[ch] = fminf(fmaxf(cc * mask, 0.0f), 1.0f);
            }
            c0 = col3[0]; c1 = col3[1]; c2 = col3[2];
        }
        out[pix * 3 + 0] = c0;
        out[pix * 3 + 1] = c1;
        out[pix * 3 + 2] = c2;
    }
}

extern "C" void kernel_launch(void* const* d_in, const int* in_sizes, int n_in,
                              void* d_out, int out_size) {
    const float* pts   = (const float*)d_in[0];
    const int*   faces = (const int*)  d_in[1];
    const float* rot   = (const float*)d_in[2];
    const float* cpos  = (const float*)d_in[3];
    const float* cproj = (const float*)d_in[4];
    const float* uv    = (const float*)d_in[5];
    const int*   ft    = (const int*)  d_in[6];
    const float* tex   = (const float*)d_in[7];

    int P = in_sizes[0] / 3;
    int F = in_sizes[1] / 3;
    int texels = in_sizes[7] / 3;
    int tw = (int)(sqrt((double)texels) + 0.5);
    int th = texels / tw;

    float* out = (float*)d_out;
    int normal_off = HEIGHT * WIDTH * 3 + HEIGHT * WIDTH;

    // single fused kernel: 32x32 tiles of 8x8 pixels
    fused_kernel<<<1024, 256>>>(pts, faces, rot, cpos, cproj, uv, ft, tex,
                                out, P, F, th, tw, normal_off);
}

// round 15
// speedup vs baseline: 1.1555x; 1.0194x over previous
#include <cuda_runtime.h>
#include <math.h>

#define EPSF      1e-10f
#define SIGINV    7000.0f
#define HEIGHT    256
#define WIDTH     256
#define MAXF      256
// logf(1e-10f)
#define LOGMIN    -23.025850929940457f
// band where log-miss contribution is non-negligible: sqrt(18/7000) ~= 0.050709
#define BANDEXP   0.0508f
// edge-line cull threshold: band + tile half-diagonal (3.5*sqrt(2)/128) + margin
#define CULLTHR   (0.0508f + 0.03867f + 0.002f)

// XLA-style contraction of a*b - c*d: fuse the FIRST multiply.
__device__ __forceinline__ float fused_det(float a, float b, float c, float d) {
    return __fmaf_rn(a, b, -__fmul_rn(c, d));
}

__device__ __forceinline__ float edge_d2(float rx, float ry,
                                         float ex, float ey, float inv) {
    float tt = __saturatef((rx * ex + ry * ey) * inv);
    float dx = rx - tt * ex;
    float dy = ry - tt * ey;
    return dx * dx + dy * dy;
}

// transform one vertex: EXACT op sequence of the reference pipeline
__device__ __forceinline__ void xform(const float* __restrict__ pts, int i,
                                      const float* __restrict__ rot,
                                      const float* __restrict__ cpos,
                                      const float* __restrict__ cproj,
                                      float& sx, float& sy, float& cz) {
    float a0 = __fsub_rn(pts[i * 3 + 0], cpos[0]);
    float a1 = __fsub_rn(pts[i * 3 + 1], cpos[1]);
    float a2 = __fsub_rn(pts[i * 3 + 2], cpos[2]);
    float q0 = __fmaf_rn(a2, rot[2], __fmaf_rn(a1, rot[1], __fmul_rn(a0, rot[0])));
    float q1 = __fmaf_rn(a2, rot[5], __fmaf_rn(a1, rot[4], __fmul_rn(a0, rot[3])));
    float q2 = __fmaf_rn(a2, rot[8], __fmaf_rn(a1, rot[7], __fmul_rn(a0, rot[6])));
    float x3 = __fmul_rn(q0, cproj[0]);
    float y3 = __fmul_rn(q1, cproj[1]);
    float z3 = __fmul_rn(q2, cproj[2]);
    sx = __fdiv_rn(x3, z3);
    sy = __fdiv_rn(y3, z3);
    cz = q2;
}

// ONE fused kernel: each block = 8x8 pixel tile. One thread per face does
// the vertex transforms + face setup directly in registers (redundant across
// blocks but cheap), prefilters vs tile bbox + edge-line distance, compacts
// survivors to shared, then the 4-chunk warp-pure face loop. improb uses
// the product form (== exp of the log-sum) with fast __expf in the band arm.
__global__ void __launch_bounds__(256)
fused_kernel(const float* __restrict__ pts,
             const int*   __restrict__ faces,
             const float* __restrict__ rot,
             const float* __restrict__ cpos,
             const float* __restrict__ cproj,
             const float* __restrict__ uv,
             const int*   __restrict__ ft,
             const float* __restrict__ tex,
             float* __restrict__ out,
             int P, int F, int th, int tw, int normal_off) {
    __shared__ float4 s0[MAXF], s1[MAXF], s2[MAXF];
    __shared__ float  si[MAXF];
    __shared__ int    sidx[MAXF];
    __shared__ int    wbase[9];
    __shared__ float4 r4[4][64];
    __shared__ int    rk[4][64];
    __shared__ int    rc[4][64];

    int t = threadIdx.x;
    int ti = blockIdx.x >> 5;   // tile row
    int tj = blockIdx.x & 31;   // tile col

    // tile pixel-center bounds
    float txlo = ((float)(tj * 8) + 0.5f) * (1.0f / 128.0f) - 1.0f;
    float txhi = ((float)(tj * 8 + 7) + 0.5f) * (1.0f / 128.0f) - 1.0f;
    float tyhi = 1.0f - (((float)(ti * 8) + 0.5f) * (1.0f / 128.0f));
    float tylo = 1.0f - (((float)(ti * 8 + 7) + 0.5f) * (1.0f / 128.0f));
    float pcx = 0.5f * (txlo + txhi);
    float pcy = 0.5f * (tylo + tyhi);

    // ---- per-face setup, one thread per face, all in registers ----
    bool have = t < F;
    float x0=0,y0=0,x1=0,y1=0,x2=0,y2=0,p0z=0,p1z=0,p2z=0,invA=0,sA=1.0f;
    bool keep = false;

    if (have) {
        int i0 = __ldg(&faces[t * 3 + 0]);
        int i1 = __ldg(&faces[t * 3 + 1]);
        int i2 = __ldg(&faces[t * 3 + 2]);
        xform(pts, i0, rot, cpos, cproj, x0, y0, p0z);
        xform(pts, i1, rot, cpos, cproj, x1, y1, p1z);
        xform(pts, i2, rot, cpos, cproj, x2, y2, p2z);

        // camera-space deltas for the normal (recompute q from pts exactly)
        // cross(p1-p0, p2-p0): need full camera-space coords.
        float b0x = __fsub_rn(pts[i0*3+0], cpos[0]);
        float b0y = __fsub_rn(pts[i0*3+1], cpos[1]);
        float b0z = __fsub_rn(pts[i0*3+2], cpos[2]);
        float b1x = __fsub_rn(pts[i1*3+0], cpos[0]);
        float b1y = __fsub_rn(pts[i1*3+1], cpos[1]);
        float b1z = __fsub_rn(pts[i1*3+2], cpos[2]);
        float b2x = __fsub_rn(pts[i2*3+0], cpos[0]);
        float b2y = __fsub_rn(pts[i2*3+1], cpos[1]);
        float b2z = __fsub_rn(pts[i2*3+2], cpos[2]);
        float p0x = __fmaf_rn(b0z, rot[2], __fmaf_rn(b0y, rot[1], __fmul_rn(b0x, rot[0])));
        float p0y = __fmaf_rn(b0z, rot[5], __fmaf_rn(b0y, rot[4], __fmul_rn(b0x, rot[3])));
        float p1x = __fmaf_rn(b1z, rot[2], __fmaf_rn(b1y, rot[1], __fmul_rn(b1x, rot[0])));
        float p1y = __fmaf_rn(b1z, rot[5], __fmaf_rn(b1y, rot[4], __fmul_rn(b1x, rot[3])));
        float p2x = __fmaf_rn(b2z, rot[2], __fmaf_rn(b2y, rot[1], __fmul_rn(b2x, rot[0])));
        float p2y = __fmaf_rn(b2z, rot[5], __fmaf_rn(b2y, rot[4], __fmul_rn(b2x, rot[3])));

        float d1x = __fsub_rn(p1x, p0x), d1y = __fsub_rn(p1y, p0y), d1z = __fsub_rn(p1z, p0z);
        float d2x = __fsub_rn(p2x, p0x), d2y = __fsub_rn(p2y, p0y), d2z = __fsub_rn(p2z, p0z);
        float nx = fused_det(d1y, d2z, d1z, d2y);
        float ny = fused_det(d1z, d2x, d1x, d2z);
        float nz = fused_det(d1x, d2y, d1y, d2x);

        if (blockIdx.x == 0) {
            float ss = __fmaf_rn(nz, nz, __fmaf_rn(ny, ny, __fmul_rn(nx, nx)));
            float nn = __fsqrt_rn(ss);
            float den = __fadd_rn(nn, EPSF);
            out[normal_off + t * 3 + 0] = __fdiv_rn(nx, den);
            out[normal_off + t * 3 + 1] = __fdiv_rn(ny, den);
            out[normal_off + t * 3 + 2] = __fdiv_rn(nz, den);
        }

        float A = fused_det(__fsub_rn(x1, x0), __fsub_rn(y2, y0),
                            __fsub_rn(x2, x0), __fsub_rn(y1, y0));
        bool aok = fabsf(A) > EPSF;
        invA = aok ? __fdiv_rn(1.0f, A) : 0.0f;
        sA = (A > 0.0f) ? 1.0f : -1.0f;
        bool valid = aok && (nz > 0.0f);

        if (valid) {
            float xlo = fminf(x0, fminf(x1, x2)) - BANDEXP;
            float xhi = fmaxf(x0, fmaxf(x1, x2)) + BANDEXP;
            float ylo = fminf(y0, fminf(y1, y2)) - BANDEXP;
            float yhi = fmaxf(y0, fmaxf(y1, y2)) + BANDEXP;
            bool bok = !(xhi < txlo || xlo > txhi || yhi < tylo || ylo > tyhi);
            if (bok) {
                float e01x = x1 - x0, e01y = y1 - y0;
                float e12x = x2 - x1, e12y = y2 - y1;
                float e20x = x0 - x2, e20y = y0 - y2;
                float i01 = 1.0f / (e01x * e01x + e01y * e01y + EPSF);
                float i12 = 1.0f / (e12x * e12x + e12y * e12y + EPSF);
                float i20 = 1.0f / (e20x * e20x + e20y * e20y + EPSF);
                float c01 = e01x * (pcy - y0) - e01y * (pcx - x0);
                float c12 = e12x * (pcy - y1) - e12y * (pcx - x1);
                float c20 = e20x * (pcy - y2) - e20y * (pcx - x2);
                float d01 = -sA * c01 * sqrtf(i01);
                float d12 = -sA * c12 * sqrtf(i12);
                float d20 = -sA * c20 * sqrtf(i20);
                keep = fmaxf(d01, fmaxf(d12, d20)) <= CULLTHR;
            }
        }
    }

    // order-preserving compaction of kept faces into shared survivor arrays
    unsigned m = __ballot_sync(0xffffffffu, keep);
    int lane = t & 31, warp = t >> 5;
    int pre = __popc(m & ((1u << lane) - 1u));
    if (lane == 0) wbase[warp + 1] = __popc(m);
    __syncthreads();
    if (t == 0) {
        wbase[0] = 0;
        #pragma unroll
        for (int w = 0; w < 8; w++) wbase[w + 1] += wbase[w];
    }
    __syncthreads();
    if (keep) {
        int c = wbase[warp] + pre;
        float e01x = x1 - x0, e01y = y1 - y0;
        float e12x = x2 - x1, e12y = y2 - y1;
        float e20x = x0 - x2, e20y = y0 - y2;
        float i01 = 1.0f / (e01x * e01x + e01y * e01y + EPSF);
        float i12 = 1.0f / (e12x * e12x + e12y * e12y + EPSF);
        float i20 = 1.0f / (e20x * e20x + e20y * e20y + EPSF);
        s0[c] = make_float4(x0, y0, x1, y1);
        s1[c] = make_float4(x2, y2, p0z, p1z);
        s2[c] = make_float4(p2z, invA, i01, i12);
        si[c] = i20;
        sidx[c] = t;
    }
    __syncthreads();
    int ns = wbase[8];

    // ---- face loop ----
    int p = t & 63;             // pixel within tile
    int chunk = t >> 6;         // 0..3; warp-pure
    int row = ti * 8 + (p >> 3);
    int col = tj * 8 + (p & 7);
    float px = ((float)col + 0.5f) * (1.0f / 128.0f) - 1.0f;
    float py = 1.0f - ((float)row + 0.5f) * (1.0f / 128.0f);

    int q = (ns + 3) >> 2;
    int kbeg = chunk * q;
    int kend = min(kbeg + q, ns);

    float prod = 1.0f;          // product of miss probs (== exp of log-sum)
    int   cnt = 0;
    float bz = -1e10f, bw0 = 0.0f, bw1 = 0.0f;
    int bk = -1;

    for (int k = kbeg; k < kend; k++) {
        float4 A4 = s0[k];
        float4 B4 = s1[k];
        float4 C4 = s2[k];
        float r0x = __fsub_rn(px, A4.x), r0y = __fsub_rn(py, A4.y);
        float r1x = __fsub_rn(px, A4.z), r1y = __fsub_rn(py, A4.w);
        float r2x = __fsub_rn(px, B4.x), r2y = __fsub_rn(py, B4.y);
        float invAk = C4.y;
        float w0 = __fmul_rn(fused_det(r1x, r2y, r2x, r1y), invAk);
        float w1 = __fmul_rn(fused_det(r2x, r0y, r0x, r2y), invAk);
        float w2 = __fsub_rn(__fsub_rn(1.0f, w0), w1);
        bool inside = (w0 >= 0.0f) && (w1 >= 0.0f) && (w2 >= 0.0f);

        if (inside) {
            float z = __fmaf_rn(w2, C4.x, __fmaf_rn(w0, B4.z, __fmul_rn(w1, B4.w)));
            if (z > bz) { bz = z; bk = k; bw0 = w0; bw1 = w1; }
            cnt++;
        } else {
            float e01x = r0x - r1x, e01y = r0y - r1y;
            float e12x = r1x - r2x, e12y = r1y - r2y;
            float e20x = r2x - r0x, e20y = r2y - r0y;
            float d2 = edge_d2(r0x, r0y, e01x, e01y, C4.z);
            d2 = fminf(d2, edge_d2(r1x, r1y, e12x, e12y, C4.w));
            d2 = fminf(d2, edge_d2(r2x, r2y, e20x, e20y, si[k]));
            float aa = d2 * SIGINV;
            if (aa < 18.0f) {
                // miss prob factor; contribution for aa>=18 is |1-m|<1.6e-8
                prod *= fmaxf(1.0f - __expf(-aa), 1e-10f);
            }
        }
    }

    r4[chunk][p] = make_float4(prod, bz, bw0, bw1);
    rk[chunk][p] = bk;
    rc[chunk][p] = cnt;
    __syncthreads();

    if (t < 64) {
        float4 R = r4[0][t];
        float fprod = R.x, fz = R.y, fw0 = R.z, fw1 = R.w;
        int fk = rk[0][t];
        int fcnt = rc[0][t];
        #pragma unroll
        for (int c = 1; c < 4; c++) {
            float4 O = r4[c][t];
            fprod *= O.x;
            fcnt += rc[c][t];
            // ascending chunk order -> strict > keeps first occurrence
            if (O.y > fz) { fz = O.y; fk = rk[c][t]; fw0 = O.z; fw1 = O.w; }
        }

        int prow = ti * 8 + (t >> 3);
        int pcol = tj * 8 + (t & 7);
        int pix = prow * 256 + pcol;

        // improb = 1 - prod * (1e-10)^cnt
        float hitfac = (fcnt > 0) ? expf((float)fcnt * LOGMIN) : 1.0f;
        out[HEIGHT * WIDTH * 3 + pix] = 1.0f - fprod * hitfac;

        // fragment shader
        float c0 = 0.0f, c1 = 0.0f, c2 = 0.0f;
        if (fk >= 0) {
            int bf = sidx[fk];
            int t0 = __ldg(&ft[bf * 3 + 0]);
            int t1 = __ldg(&ft[bf * 3 + 1]);
            int t2 = __ldg(&ft[bf * 3 + 2]);
            float u0 = __ldg(&uv[t0 * 2]), v0 = __ldg(&uv[t0 * 2 + 1]);
            float u1 = __ldg(&uv[t1 * 2]), v1 = __ldg(&uv[t1 * 2 + 1]);
            float u2 = __ldg(&uv[t2 * 2]), v2 = __ldg(&uv[t2 * 2 + 1]);
            float fw2 = __fsub_rn(__fsub_rn(1.0f, fw0), fw1);
            float u = __fmaf_rn(fw2, u2, __fmaf_rn(fw0, u0, __fmul_rn(fw1, u1)));
            float v = __fmaf_rn(fw2, v2, __fmaf_rn(fw0, v0, __fmul_rn(fw1, v1)));
            float mask = __fadd_rn(__fadd_rn(fw0, fw1), fw2);

            float x = u * (float)(tw - 1);
            float y = (1.0f - v) * (float)(th - 1);
            float x0f = fminf(fmaxf(floorf(x), 0.0f), (float)(tw - 1));
            float y0f = fminf(fmaxf(floorf(y), 0.0f), (float)(th - 1));
            int x0i = (int)x0f, y0i = (int)y0f;
            int x1i = min(x0i + 1, tw - 1);
            int y1i = min(y0i + 1, th - 1);
            float wx = fminf(fmaxf(x - x0f, 0.0f), 1.0f);
            float wy = fminf(fmaxf(y - y0f, 0.0f), 1.0f);

            int cs = th * tw;
            int b00 = y0i * tw + x0i, b01 = y0i * tw + x1i;
            int b10 = y1i * tw + x0i, b11 = y1i * tw + x1i;

            float col3[3];
            #pragma unroll
            for (int ch = 0; ch < 3; ch++) {
                const float* tc = tex + ch * cs;
                float v00 = __ldg(tc + b00), v01 = __ldg(tc + b01);
                float v10 = __ldg(tc + b10), v11 = __ldg(tc + b11);
                float cc = (v00 * (1.0f - wx) + v01 * wx) * (1.0f - wy)
                         + (v10 * (1.0f - wx) + v11 * wx) * wy;
                col3[ch] = fminf(fmaxf(cc * mask, 0.0f), 1.0f);
            }
            c0 = col3[0]; c1 = col3[1]; c2 = col3[2];
        }
        out[pix * 3 + 0] = c0;
        out[pix * 3 + 1] = c1;
        out[pix * 3 + 2] = c2;
    }
}

extern "C" void kernel_launch(void* const* d_in, const int* in_sizes, int n_in,
                              void* d_out, int out_size) {
    const float* pts   = (const float*)d_in[0];
    const int*   faces = (const int*)  d_in[1];
    const float* rot   = (const float*)d_in[2];
    const float* cpos  = (const float*)d_in[3];
    const float* cproj = (const float*)d_in[4];
    const float* uv    = (const float*)d_in[5];
    const int*   ft    = (const int*)  d_in[6];
    const float* tex   = (const float*)d_in[7];

    int P = in_sizes[0] / 3;
    int F = in_sizes[1] / 3;
    int texels = in_sizes[7] / 3;
    int tw = (int)(sqrt((double)texels) + 0.5);
    int th = texels / tw;

    float* out = (float*)d_out;
    int normal_off = HEIGHT * WIDTH * 3 + HEIGHT * WIDTH;

    // single fused kernel: 32x32 tiles of 8x8 pixels
    fused_kernel<<<1024, 256>>>(pts, faces, rot, cpos, cproj, uv, ft, tex,
                                out, P, F, th, tw, normal_off);
}